// round 1
// baseline (speedup 1.0000x reference)
#include <cuda_runtime.h>
#include <math.h>

#define FULLMASK 0xffffffffu

constexpr int B_ROWS = 262144;
constexpr int IN_DIM = 96;

// packed fp32x2 FMA (sm_100+): d = a*b + c per 32-bit half
__device__ __forceinline__ unsigned long long ffma2(unsigned long long a,
                                                    unsigned long long b,
                                                    unsigned long long c) {
    unsigned long long d;
    asm("fma.rn.f32x2 %0, %1, %2, %3;" : "=l"(d) : "l"(a), "l"(b), "l"(c));
    return d;
}

__global__ void __launch_bounds__(256)
actor_fused_kernel(
    const float* __restrict__ s_input,
    const float* __restrict__ en_W1,  const float* __restrict__ en_b1,
    const float* __restrict__ en_W2,  const float* __restrict__ en_b2,
    const float* __restrict__ oa_W1,  const float* __restrict__ oa_b1,
    const float* __restrict__ oa_W2,  const float* __restrict__ oa_b2,
    const float* __restrict__ goal_W1,const float* __restrict__ goal_b1,
    const float* __restrict__ goal_W2,const float* __restrict__ goal_b2,
    const float* __restrict__ oa_ln_g,const float* __restrict__ oa_ln_b,
    const float* __restrict__ goal_ln_g,const float* __restrict__ goal_ln_b,
    const float* __restrict__ act_W1, const float* __restrict__ act_b1,
    const float* __restrict__ act_W2, const float* __restrict__ act_b2,
    const float* __restrict__ act_W3, const float* __restrict__ act_b3,
    float* __restrict__ out)
{
    // group g: 0 = oa (other agents, lanes 0-14), 1 = en (self, lane 15), 2 = goal (food, lanes 16-31)
    __shared__ __align__(16) float sW1T[3 * 32 * 4];   // [g][j][i]  (transposed, goal padded to 4 inputs)
    __shared__ float               sB1 [3 * 32];
    __shared__ __align__(16) float sW2 [3 * 32 * 16];  // [g][j][d]
    __shared__ __align__(16) float sB2 [3 * 16];
    __shared__ float sLNg[2 * 16], sLNb[2 * 16];       // [half: 0=oa,1=goal][d]
    __shared__ float sAW1[48 * 32], sAB1[32];
    __shared__ float sAW2[32 * 32], sAB2[32];
    __shared__ float sAW3[32 * 2],  sAB3[2];

    const int t = threadIdx.x;
    // ---- stage weights into shared ----
    for (int idx = t; idx < 3 * 32 * 4; idx += blockDim.x) {
        int gg = idx >> 7, r = idx & 127, j = r >> 2, i = r & 3;
        float v;
        if (gg == 0)      v = oa_W1[i * 32 + j];
        else if (gg == 1) v = en_W1[i * 32 + j];
        else              v = (i < 2) ? goal_W1[i * 32 + j] : 0.f;
        sW1T[idx] = v;
    }
    for (int idx = t; idx < 96; idx += blockDim.x) {
        int gg = idx >> 5, j = idx & 31;
        sB1[idx] = (gg == 0 ? oa_b1 : gg == 1 ? en_b1 : goal_b1)[j];
    }
    for (int idx = t; idx < 3 * 512; idx += blockDim.x) {
        int gg = idx >> 9, r = idx & 511;
        sW2[idx] = (gg == 0 ? oa_W2 : gg == 1 ? en_W2 : goal_W2)[r];
    }
    for (int idx = t; idx < 48; idx += blockDim.x) {
        int gg = idx >> 4, j = idx & 15;
        sB2[idx] = (gg == 0 ? oa_b2 : gg == 1 ? en_b2 : goal_b2)[j];
    }
    if (t < 16) {
        sLNg[t]      = oa_ln_g[t];   sLNb[t]      = oa_ln_b[t];
        sLNg[16 + t] = goal_ln_g[t]; sLNb[16 + t] = goal_ln_b[t];
    }
    for (int idx = t; idx < 1536; idx += blockDim.x) sAW1[idx] = act_W1[idx];
    for (int idx = t; idx < 1024; idx += blockDim.x) sAW2[idx] = act_W2[idx];
    if (t < 32) { sAB1[t] = act_b1[t]; sAB2[t] = act_b2[t]; }
    if (t < 64) sAW3[t] = act_W3[t];
    if (t < 2)  sAB3[t] = act_b3[t];
    __syncthreads();

    const int lane  = t & 31;
    const int gwarp = (blockIdx.x * blockDim.x + t) >> 5;
    const int nwarp = (gridDim.x * blockDim.x) >> 5;

    const int g = (lane < 15) ? 0 : ((lane == 15) ? 1 : 2);
    const float4*             w1p = reinterpret_cast<const float4*>(sW1T + g * 128);
    const float*              b1p = sB1 + g * 32;
    const unsigned long long* w2p = reinterpret_cast<const unsigned long long*>(sW2 + g * 512);
    const unsigned long long* b2p = reinterpret_cast<const unsigned long long*>(sB2 + g * 16);
    const int half = lane >> 4;

    for (int row = gwarp; row < B_ROWS; row += nwarp) {
        const float* rb = s_input + (size_t)row * IN_DIM;

        // ---- per-lane item input ----
        float x0, x1, x2, x3;
        if (lane < 15) {
            float2 a = *reinterpret_cast<const float2*>(rb + 4 + 2 * lane);
            float2 b = *reinterpret_cast<const float2*>(rb + 34 + 2 * lane);
            x0 = a.x; x1 = a.y; x2 = b.x; x3 = b.y;
        } else if (lane == 15) {
            float4 v = *reinterpret_cast<const float4*>(rb);
            x0 = v.x; x1 = v.y; x2 = v.z; x3 = v.w;
        } else {
            float2 v = *reinterpret_cast<const float2*>(rb + 64 + 2 * (lane - 16));
            x0 = v.x; x1 = v.y; x2 = 0.f; x3 = 0.f;
        }

        // ---- encoder MLP (per-lane item): 4->32 relu -> 16, layer2 packed f32x2 ----
        unsigned long long acc[8];
        #pragma unroll
        for (int q = 0; q < 8; q++) acc[q] = b2p[q];
        #pragma unroll
        for (int j = 0; j < 32; j++) {
            float4 w = w1p[j];
            float hj = b1p[j];
            hj = fmaf(x0, w.x, hj); hj = fmaf(x1, w.y, hj);
            hj = fmaf(x2, w.z, hj); hj = fmaf(x3, w.w, hj);
            hj = fmaxf(hj, 0.f);
            unsigned hb = __float_as_uint(hj);
            unsigned long long hh;
            asm("mov.b64 %0, {%1, %2};" : "=l"(hh) : "r"(hb), "r"(hb));
            #pragma unroll
            for (int q = 0; q < 8; q++) acc[q] = ffma2(hh, w2p[j * 8 + q], acc[q]);
        }
        float e[16];
        #pragma unroll
        for (int q = 0; q < 8; q++) {
            unsigned lo, hi;
            asm("mov.b64 {%0, %1}, %2;" : "=r"(lo), "=r"(hi) : "l"(acc[q]));
            e[2 * q]     = fmaxf(__uint_as_float(lo), 0.f);
            e[2 * q + 1] = fmaxf(__uint_as_float(hi), 0.f);
        }

        // ---- broadcast self encoding (lane 15) ----
        float so[16];
        #pragma unroll
        for (int d = 0; d < 16; d++) so[d] = __shfl_sync(FULLMASK, e[d], 15);

        // ---- attention scores + softmax within each 16-lane half (lane 15 masked) ----
        float sc = 0.f;
        #pragma unroll
        for (int d = 0; d < 16; d++) sc = fmaf(so[d], e[d], sc);
        sc *= 0.25f;                                  // SCALE = 1/sqrt(16)
        const bool active = (lane != 15);
        float scm = active ? sc : -INFINITY;
        float mx = scm;
        #pragma unroll
        for (int o = 1; o < 16; o <<= 1) mx = fmaxf(mx, __shfl_xor_sync(FULLMASK, mx, o));
        float p = active ? __expf(scm - mx) : 0.f;
        float ps = p;
        #pragma unroll
        for (int o = 1; o < 16; o <<= 1) ps += __shfl_xor_sync(FULLMASK, ps, o);
        const float aw = p / ps;

        // ---- attention-weighted pool (butterfly over the half-warp) ----
        float pv[16];
        #pragma unroll
        for (int d = 0; d < 16; d++) pv[d] = aw * e[d];
        #pragma unroll
        for (int o = 1; o < 16; o <<= 1) {
            #pragma unroll
            for (int d = 0; d < 16; d++) pv[d] += __shfl_xor_sync(FULLMASK, pv[d], o);
        }

        // ---- LayerNorm + relu on own half's pool ----
        float mu = 0.f;
        #pragma unroll
        for (int d = 0; d < 16; d++) mu += pv[d];
        mu *= (1.f / 16.f);
        float var = 0.f;
        #pragma unroll
        for (int d = 0; d < 16; d++) { float tt = pv[d] - mu; var = fmaf(tt, tt, var); }
        var *= (1.f / 16.f);
        const float inv = rsqrtf(var + 1e-5f);
        float myp[16];
        #pragma unroll
        for (int d = 0; d < 16; d++)
            myp[d] = fmaxf(fmaf((pv[d] - mu) * inv, sLNg[half * 16 + d], sLNb[half * 16 + d]), 0.f);

        // ---- swap pools across half-warps ----
        float op[16];
        #pragma unroll
        for (int d = 0; d < 16; d++) op[d] = __shfl_xor_sync(FULLMASK, myp[d], 16);
        const bool lower = (lane < 16);
        float fpool[16], opool[16];
        #pragma unroll
        for (int d = 0; d < 16; d++) {
            fpool[d] = lower ? op[d]  : myp[d];   // food pool (goal LN)
            opool[d] = lower ? myp[d] : op[d];    // other pool (oa LN)
        }

        // ---- head: merged(48)=[self,food,other] -> 32 -> 32 -> 2 ----
        float hv = sAB1[lane];
        #pragma unroll
        for (int d = 0; d < 16; d++) hv = fmaf(so[d],    sAW1[d * 32 + lane],        hv);
        #pragma unroll
        for (int d = 0; d < 16; d++) hv = fmaf(fpool[d], sAW1[(16 + d) * 32 + lane], hv);
        #pragma unroll
        for (int d = 0; d < 16; d++) hv = fmaf(opool[d], sAW1[(32 + d) * 32 + lane], hv);
        hv = fmaxf(hv, 0.01f * hv);                    // leaky_relu(0.01)

        float h2 = sAB2[lane];
        #pragma unroll
        for (int j = 0; j < 32; j++)
            h2 = fmaf(__shfl_sync(FULLMASK, hv, j), sAW2[j * 32 + lane], h2);
        h2 = fmaxf(h2, 0.01f * h2);

        float p0 = h2 * sAW3[lane * 2 + 0];
        float p1 = h2 * sAW3[lane * 2 + 1];
        #pragma unroll
        for (int o = 16; o >= 1; o >>= 1) {
            p0 += __shfl_xor_sync(FULLMASK, p0, o);
            p1 += __shfl_xor_sync(FULLMASK, p1, o);
        }
        if (lane == 0) {
            float2 r;
            r.x = tanhf(p0 + sAB3[0]);
            r.y = tanhf(p1 + sAB3[1]);
            *reinterpret_cast<float2*>(out + (size_t)row * 2) = r;
        }
    }
}

extern "C" void kernel_launch(void* const* d_in, const int* in_sizes, int n_in,
                              void* d_out, int out_size) {
    (void)in_sizes; (void)n_in; (void)out_size;
    dim3 grid(592), block(256);   // persistent-ish grid-stride; ~4736 warps, ~55 rows/warp
    actor_fused_kernel<<<grid, block>>>(
        (const float*)d_in[0],
        (const float*)d_in[1],  (const float*)d_in[2],
        (const float*)d_in[3],  (const float*)d_in[4],
        (const float*)d_in[5],  (const float*)d_in[6],
        (const float*)d_in[7],  (const float*)d_in[8],
        (const float*)d_in[9],  (const float*)d_in[10],
        (const float*)d_in[11], (const float*)d_in[12],
        (const float*)d_in[13], (const float*)d_in[14],
        (const float*)d_in[15], (const float*)d_in[16],
        (const float*)d_in[17], (const float*)d_in[18],
        (const float*)d_in[19], (const float*)d_in[20],
        (const float*)d_in[21], (const float*)d_in[22],
        (float*)d_out);
}

// round 2
// speedup vs baseline: 2.0646x; 2.0646x over previous
#include <cuda_runtime.h>
#include <math.h>

#define FULLMASK 0xffffffffu

constexpr int B_ROWS = 262144;
constexpr int IN_DIM = 96;
constexpr int R = 4;           // rows per warp per iteration (amortizes weight LDS)

__device__ __forceinline__ unsigned long long ffma2(unsigned long long a,
                                                    unsigned long long b,
                                                    unsigned long long c) {
    unsigned long long d;
    asm("fma.rn.f32x2 %0, %1, %2, %3;" : "=l"(d) : "l"(a), "l"(b), "l"(c));
    return d;
}

__global__ void __launch_bounds__(256)
actor_fused_kernel(
    const float* __restrict__ s_input,
    const float* __restrict__ en_W1,  const float* __restrict__ en_b1,
    const float* __restrict__ en_W2,  const float* __restrict__ en_b2,
    const float* __restrict__ oa_W1,  const float* __restrict__ oa_b1,
    const float* __restrict__ oa_W2,  const float* __restrict__ oa_b2,
    const float* __restrict__ goal_W1,const float* __restrict__ goal_b1,
    const float* __restrict__ goal_W2,const float* __restrict__ goal_b2,
    const float* __restrict__ oa_ln_g,const float* __restrict__ oa_ln_b,
    const float* __restrict__ goal_ln_g,const float* __restrict__ goal_ln_b,
    const float* __restrict__ act_W1, const float* __restrict__ act_b1,
    const float* __restrict__ act_W2, const float* __restrict__ act_b2,
    const float* __restrict__ act_W3, const float* __restrict__ act_b3,
    float* __restrict__ out)
{
    // group g: 0 = oa (lanes 0-14), 1 = en/self (lane 15), 2 = goal (lanes 16-31)
    __shared__ __align__(16) float sW1T[3 * 32 * 4];   // [g][j][i] transposed
    __shared__ float               sB1 [3 * 32];
    __shared__ __align__(16) float sW2 [3 * 32 * 16];  // [g][j][d]
    __shared__ __align__(16) float sB2 [3 * 16];
    __shared__ float sLN_g[32], sLN_b[32];             // [lane]: 0-15 oa, 16-31 goal
    __shared__ float sAW1[48 * 32], sAB1[32];
    __shared__ float sAW2[32 * 32], sAB2[32];
    __shared__ float sAW3[32 * 2],  sAB3[2];

    const int t = threadIdx.x;
    for (int idx = t; idx < 3 * 32 * 4; idx += blockDim.x) {
        int gg = idx >> 7, r = idx & 127, j = r >> 2, i = r & 3;
        float v;
        if (gg == 0)      v = oa_W1[i * 32 + j];
        else if (gg == 1) v = en_W1[i * 32 + j];
        else              v = (i < 2) ? goal_W1[i * 32 + j] : 0.f;
        sW1T[idx] = v;
    }
    for (int idx = t; idx < 96; idx += blockDim.x) {
        int gg = idx >> 5, j = idx & 31;
        sB1[idx] = (gg == 0 ? oa_b1 : gg == 1 ? en_b1 : goal_b1)[j];
    }
    for (int idx = t; idx < 3 * 512; idx += blockDim.x) {
        int gg = idx >> 9, r = idx & 511;
        sW2[idx] = (gg == 0 ? oa_W2 : gg == 1 ? en_W2 : goal_W2)[r];
    }
    for (int idx = t; idx < 48; idx += blockDim.x) {
        int gg = idx >> 4, j = idx & 15;
        sB2[idx] = (gg == 0 ? oa_b2 : gg == 1 ? en_b2 : goal_b2)[j];
    }
    if (t < 16) {
        sLN_g[t]      = oa_ln_g[t];   sLN_b[t]      = oa_ln_b[t];
        sLN_g[16 + t] = goal_ln_g[t]; sLN_b[16 + t] = goal_ln_b[t];
    }
    for (int idx = t; idx < 1536; idx += blockDim.x) sAW1[idx] = act_W1[idx];
    for (int idx = t; idx < 1024; idx += blockDim.x) sAW2[idx] = act_W2[idx];
    if (t < 32) { sAB1[t] = act_b1[t]; sAB2[t] = act_b2[t]; }
    if (t < 64) sAW3[t] = act_W3[t];
    if (t < 2)  sAB3[t] = act_b3[t];
    __syncthreads();

    const int lane  = t & 31;
    const int q16   = lane & 15;           // id within 16-lane half
    const int gwarp = (blockIdx.x * blockDim.x + t) >> 5;
    const int nwarp = (gridDim.x * blockDim.x) >> 5;

    const int g = (lane < 15) ? 0 : ((lane == 15) ? 1 : 2);
    const float4*             w1p = reinterpret_cast<const float4*>(sW1T + g * 128);
    const float*              b1p = sB1 + g * 32;
    const unsigned long long* w2p = reinterpret_cast<const unsigned long long*>(sW2 + g * 512);
    const unsigned long long* b2p = reinterpret_cast<const unsigned long long*>(sB2 + g * 16);
    const bool lower = (lane < 16);

    // per-lane constants hoisted out of the row loop
    const float lnG = sLN_g[lane], lnB = sLN_b[lane];
    const float aB1 = sAB1[lane],  aB2 = sAB2[lane];
    const float w3a = sAW3[lane * 2 + 0], w3b = sAW3[lane * 2 + 1];
    const float b3a = sAB3[0], b3b = sAB3[1];

    for (int row0 = gwarp * R; row0 < B_ROWS; row0 += nwarp * R) {
        // ---- per-lane item inputs for R rows ----
        float x0[R], x1[R], x2[R], x3[R];
        #pragma unroll
        for (int r = 0; r < R; r++) {
            const float* rb = s_input + (size_t)(row0 + r) * IN_DIM;
            if (lane < 15) {
                float2 a = *reinterpret_cast<const float2*>(rb + 4 + 2 * lane);
                float2 b = *reinterpret_cast<const float2*>(rb + 34 + 2 * lane);
                x0[r] = a.x; x1[r] = a.y; x2[r] = b.x; x3[r] = b.y;
            } else if (lane == 15) {
                float4 v = *reinterpret_cast<const float4*>(rb);
                x0[r] = v.x; x1[r] = v.y; x2[r] = v.z; x3[r] = v.w;
            } else {
                float2 v = *reinterpret_cast<const float2*>(rb + 64 + 2 * (lane - 16));
                x0[r] = v.x; x1[r] = v.y; x2[r] = 0.f; x3[r] = 0.f;
            }
        }

        // ---- encoder MLP for R rows, weights loaded once per j ----
        unsigned long long acc[R][8];
        #pragma unroll
        for (int r = 0; r < R; r++)
            #pragma unroll
            for (int qq = 0; qq < 8; qq++) acc[r][qq] = b2p[qq];

        #pragma unroll
        for (int j = 0; j < 32; j++) {
            float4 w = w1p[j];
            float bj = b1p[j];
            unsigned long long w2r[8];
            #pragma unroll
            for (int qq = 0; qq < 8; qq++) w2r[qq] = w2p[j * 8 + qq];
            #pragma unroll
            for (int r = 0; r < R; r++) {
                float hj = bj;
                hj = fmaf(x0[r], w.x, hj); hj = fmaf(x1[r], w.y, hj);
                hj = fmaf(x2[r], w.z, hj); hj = fmaf(x3[r], w.w, hj);
                hj = fmaxf(hj, 0.f);
                unsigned hb = __float_as_uint(hj);
                unsigned long long hh;
                asm("mov.b64 %0, {%1, %2};" : "=l"(hh) : "r"(hb), "r"(hb));
                #pragma unroll
                for (int qq = 0; qq < 8; qq++) acc[r][qq] = ffma2(hh, w2r[qq], acc[r][qq]);
            }
        }

        // ---- per-row attention / LN / head ----
        #pragma unroll
        for (int r = 0; r < R; r++) {
            float e[16];
            #pragma unroll
            for (int qq = 0; qq < 8; qq++) {
                unsigned lo, hi;
                asm("mov.b64 {%0, %1}, %2;" : "=r"(lo), "=r"(hi) : "l"(acc[r][qq]));
                e[2 * qq]     = fmaxf(__uint_as_float(lo), 0.f);
                e[2 * qq + 1] = fmaxf(__uint_as_float(hi), 0.f);
            }

            // broadcast self encoding (lane 15)
            float so[16];
            #pragma unroll
            for (int d = 0; d < 16; d++) so[d] = __shfl_sync(FULLMASK, e[d], 15);

            // scores + softmax within each 16-lane half (lane 15 masked)
            float sc = 0.f;
            #pragma unroll
            for (int d = 0; d < 16; d++) sc = fmaf(so[d], e[d], sc);
            sc *= 0.25f;
            const bool active = (lane != 15);
            float scm = active ? sc : -INFINITY;
            float mx = scm;
            #pragma unroll
            for (int o = 1; o < 16; o <<= 1) mx = fmaxf(mx, __shfl_xor_sync(FULLMASK, mx, o));
            float p = active ? __expf(scm - mx) : 0.f;
            float ps = p;
            #pragma unroll
            for (int o = 1; o < 16; o <<= 1) ps += __shfl_xor_sync(FULLMASK, ps, o);
            const float aw = p / ps;

            // weighted values
            float pv[16];
            #pragma unroll
            for (int d = 0; d < 16; d++) pv[d] = aw * e[d];

            // reduce-scatter over the 16-lane half: lane ends with pooled[q16]
            // step o=8
            float A8[8];
            {
                const bool hib = (q16 & 8) != 0;
                #pragma unroll
                for (int i = 0; i < 8; i++) {
                    float keep = hib ? pv[i + 8] : pv[i];
                    float send = hib ? pv[i]     : pv[i + 8];
                    A8[i] = keep + __shfl_xor_sync(FULLMASK, send, 8);
                }
            }
            float A4[4];
            {
                const bool hib = (q16 & 4) != 0;
                #pragma unroll
                for (int i = 0; i < 4; i++) {
                    float keep = hib ? A8[i + 4] : A8[i];
                    float send = hib ? A8[i]     : A8[i + 4];
                    A4[i] = keep + __shfl_xor_sync(FULLMASK, send, 4);
                }
            }
            float A2[2];
            {
                const bool hib = (q16 & 2) != 0;
                #pragma unroll
                for (int i = 0; i < 2; i++) {
                    float keep = hib ? A2[0] * 0.f + (hib ? A4[i + 2] : A4[i]) : A4[i]; // placeholder
                    (void)keep;
                }
                const bool hb = (q16 & 2) != 0;
                #pragma unroll
                for (int i = 0; i < 2; i++) {
                    float kp = hb ? A4[i + 2] : A4[i];
                    float sd = hb ? A4[i]     : A4[i + 2];
                    A2[i] = kp + __shfl_xor_sync(FULLMASK, sd, 2);
                }
            }
            float pooled;
            {
                const bool hb = (q16 & 1) != 0;
                float kp = hb ? A2[1] : A2[0];
                float sd = hb ? A2[0] : A2[1];
                pooled = kp + __shfl_xor_sync(FULLMASK, sd, 1);
            }
            // now: lane holds pooled[d = q16] of its own half's pool

            // LayerNorm over the 16 distributed values
            float s1 = pooled;
            #pragma unroll
            for (int o = 1; o < 16; o <<= 1) s1 += __shfl_xor_sync(FULLMASK, s1, o);
            const float mu = s1 * (1.f / 16.f);
            const float tdev = pooled - mu;
            float v2 = tdev * tdev;
            #pragma unroll
            for (int o = 1; o < 16; o <<= 1) v2 += __shfl_xor_sync(FULLMASK, v2, o);
            const float inv = rsqrtf(v2 * (1.f / 16.f) + 1e-5f);
            const float myn = fmaxf(fmaf(tdev * inv, lnG, lnB), 0.f);  // normalized+relu, scalar

            // swap across halves: every lane gets both pools' value at d=q16
            const float oth = __shfl_xor_sync(FULLMASK, myn, 16);
            const float fp = lower ? oth : myn;   // food pool[q16]  (goal half)
            const float op = lower ? myn : oth;   // other pool[q16] (oa half)

            // head layer 1: merged(48) -> 32
            float hv = aB1;
            #pragma unroll
            for (int d = 0; d < 16; d++) hv = fmaf(so[d], sAW1[d * 32 + lane], hv);
            #pragma unroll
            for (int d = 0; d < 16; d++)
                hv = fmaf(__shfl_sync(FULLMASK, fp, d, 16), sAW1[(16 + d) * 32 + lane], hv);
            #pragma unroll
            for (int d = 0; d < 16; d++)
                hv = fmaf(__shfl_sync(FULLMASK, op, d, 16), sAW1[(32 + d) * 32 + lane], hv);
            hv = fmaxf(hv, 0.01f * hv);

            // head layer 2: 32 -> 32
            float h2 = aB2;
            #pragma unroll
            for (int j = 0; j < 32; j++)
                h2 = fmaf(__shfl_sync(FULLMASK, hv, j), sAW2[j * 32 + lane], h2);
            h2 = fmaxf(h2, 0.01f * h2);

            // head layer 3: 32 -> 2 + tanh
            float p0 = h2 * w3a;
            float p1 = h2 * w3b;
            #pragma unroll
            for (int o = 16; o >= 1; o >>= 1) {
                p0 += __shfl_xor_sync(FULLMASK, p0, o);
                p1 += __shfl_xor_sync(FULLMASK, p1, o);
            }
            if (lane == 0) {
                float2 rr;
                rr.x = tanhf(p0 + b3a);
                rr.y = tanhf(p1 + b3b);
                *reinterpret_cast<float2*>(out + (size_t)(row0 + r) * 2) = rr;
            }
        }
    }
}

extern "C" void kernel_launch(void* const* d_in, const int* in_sizes, int n_in,
                              void* d_out, int out_size) {
    (void)in_sizes; (void)n_in; (void)out_size;
    dim3 grid(592), block(256);
    actor_fused_kernel<<<grid, block>>>(
        (const float*)d_in[0],
        (const float*)d_in[1],  (const float*)d_in[2],
        (const float*)d_in[3],  (const float*)d_in[4],
        (const float*)d_in[5],  (const float*)d_in[6],
        (const float*)d_in[7],  (const float*)d_in[8],
        (const float*)d_in[9],  (const float*)d_in[10],
        (const float*)d_in[11], (const float*)d_in[12],
        (const float*)d_in[13], (const float*)d_in[14],
        (const float*)d_in[15], (const float*)d_in[16],
        (const float*)d_in[17], (const float*)d_in[18],
        (const float*)d_in[19], (const float*)d_in[20],
        (const float*)d_in[21], (const float*)d_in[22],
        (float*)d_out);
}

// round 3
// speedup vs baseline: 2.2877x; 1.1080x over previous
#include <cuda_runtime.h>
#include <math.h>

#define FULLMASK 0xffffffffu

constexpr int B_ROWS = 262144;
constexpr int IN_DIM = 96;
constexpr int R = 4;           // rows per warp per iteration

__device__ __forceinline__ unsigned long long ffma2(unsigned long long a,
                                                    unsigned long long b,
                                                    unsigned long long c) {
    unsigned long long d;
    asm("fma.rn.f32x2 %0, %1, %2, %3;" : "=l"(d) : "l"(a), "l"(b), "l"(c));
    return d;
}

__global__ void __launch_bounds__(128, 3)
actor_fused_kernel(
    const float* __restrict__ s_input,
    const float* __restrict__ en_W1,  const float* __restrict__ en_b1,
    const float* __restrict__ en_W2,  const float* __restrict__ en_b2,
    const float* __restrict__ oa_W1,  const float* __restrict__ oa_b1,
    const float* __restrict__ oa_W2,  const float* __restrict__ oa_b2,
    const float* __restrict__ goal_W1,const float* __restrict__ goal_b1,
    const float* __restrict__ goal_W2,const float* __restrict__ goal_b2,
    const float* __restrict__ oa_ln_g,const float* __restrict__ oa_ln_b,
    const float* __restrict__ goal_ln_g,const float* __restrict__ goal_ln_b,
    const float* __restrict__ act_W1, const float* __restrict__ act_b1,
    const float* __restrict__ act_W2, const float* __restrict__ act_b2,
    const float* __restrict__ act_W3, const float* __restrict__ act_b3,
    float* __restrict__ out)
{
    // encoder groups: 0 = oa (lanes 0-14), 1 = en/self (lane 15), 2 = goal (lanes 16-31)
    __shared__ __align__(16) float sW1T[3 * 32 * 4];   // [g][j][i]
    __shared__ float               sB1 [3 * 32];
    __shared__ __align__(16) float sW2 [3 * 32 * 16];  // [g][j][d]
    __shared__ __align__(16) float sB2 [3 * 16];
    __shared__ float sLN_g[32], sLN_b[32];
    // head weights TRANSPOSED: row = output neuron (lane), contiguous input dim
    __shared__ __align__(16) float sAW1T[32 * 52];     // [lane][d<48], pad 52 (16B-aligned rows)
    __shared__ __align__(16) float sAW2T[32 * 36];     // [lane][j<32], pad 36
    __shared__ float sAB1[32], sAB2[32], sAW3[64], sAB3[2];

    const int t = threadIdx.x;
    for (int idx = t; idx < 3 * 32 * 4; idx += blockDim.x) {
        int gg = idx >> 7, r = idx & 127, j = r >> 2, i = r & 3;
        float v;
        if (gg == 0)      v = oa_W1[i * 32 + j];
        else if (gg == 1) v = en_W1[i * 32 + j];
        else              v = (i < 2) ? goal_W1[i * 32 + j] : 0.f;
        sW1T[idx] = v;
    }
    for (int idx = t; idx < 96; idx += blockDim.x) {
        int gg = idx >> 5, j = idx & 31;
        sB1[idx] = (gg == 0 ? oa_b1 : gg == 1 ? en_b1 : goal_b1)[j];
    }
    for (int idx = t; idx < 3 * 512; idx += blockDim.x) {
        int gg = idx >> 9, r = idx & 511;
        sW2[idx] = (gg == 0 ? oa_W2 : gg == 1 ? en_W2 : goal_W2)[r];
    }
    for (int idx = t; idx < 48; idx += blockDim.x) {
        int gg = idx >> 4, j = idx & 15;
        sB2[idx] = (gg == 0 ? oa_b2 : gg == 1 ? en_b2 : goal_b2)[j];
    }
    if (t < 16) {
        sLN_g[t]      = oa_ln_g[t];   sLN_b[t]      = oa_ln_b[t];
        sLN_g[16 + t] = goal_ln_g[t]; sLN_b[16 + t] = goal_ln_b[t];
    }
    for (int idx = t; idx < 32 * 48; idx += blockDim.x) {
        int l = idx / 48, d = idx % 48;
        sAW1T[l * 52 + d] = act_W1[d * 32 + l];
    }
    for (int idx = t; idx < 32 * 32; idx += blockDim.x) {
        int l = idx >> 5, j = idx & 31;
        sAW2T[l * 36 + j] = act_W2[j * 32 + l];
    }
    if (t < 32) { sAB1[t] = act_b1[t]; sAB2[t] = act_b2[t]; }
    if (t < 64) sAW3[t] = act_W3[t];
    if (t < 2)  sAB3[t] = act_b3[t];
    __syncthreads();

    const int lane  = t & 31;
    const int q16   = lane & 15;
    const int gwarp = (blockIdx.x * blockDim.x + t) >> 5;
    const int nwarp = (gridDim.x * blockDim.x) >> 5;

    const int g = (lane < 15) ? 0 : ((lane == 15) ? 1 : 2);
    const float4*             w1p = reinterpret_cast<const float4*>(sW1T + g * 128);
    const float*              b1p = sB1 + g * 32;
    const unsigned long long* w2p = reinterpret_cast<const unsigned long long*>(sW2 + g * 512);
    const unsigned long long* b2p = reinterpret_cast<const unsigned long long*>(sB2 + g * 16);
    const bool lower = (lane < 16);

    const float4* aw1t = reinterpret_cast<const float4*>(sAW1T + lane * 52);
    const float4* aw2t = reinterpret_cast<const float4*>(sAW2T + lane * 36);
    const float lnG = sLN_g[lane], lnB = sLN_b[lane];
    const float aB1 = sAB1[lane],  aB2 = sAB2[lane];
    const float w3a = sAW3[lane * 2 + 0], w3b = sAW3[lane * 2 + 1];
    const float b3a = sAB3[0], b3b = sAB3[1];

    for (int row0 = gwarp * R; row0 < B_ROWS; row0 += nwarp * R) {
        // ---- per-lane item inputs for R rows ----
        float x0[R], x1[R], x2[R], x3[R];
        #pragma unroll
        for (int r = 0; r < R; r++) {
            const float* rb = s_input + (size_t)(row0 + r) * IN_DIM;
            if (lane < 15) {
                float2 a = *reinterpret_cast<const float2*>(rb + 4 + 2 * lane);
                float2 b = *reinterpret_cast<const float2*>(rb + 34 + 2 * lane);
                x0[r] = a.x; x1[r] = a.y; x2[r] = b.x; x3[r] = b.y;
            } else if (lane == 15) {
                float4 v = *reinterpret_cast<const float4*>(rb);
                x0[r] = v.x; x1[r] = v.y; x2[r] = v.z; x3[r] = v.w;
            } else {
                float2 v = *reinterpret_cast<const float2*>(rb + 64 + 2 * (lane - 16));
                x0[r] = v.x; x1[r] = v.y; x2[r] = 0.f; x3[r] = 0.f;
            }
        }

        // ---- encoder MLP for R rows, weights loaded once per j ----
        unsigned long long acc[R][8];
        #pragma unroll
        for (int r = 0; r < R; r++)
            #pragma unroll
            for (int qq = 0; qq < 8; qq++) acc[r][qq] = b2p[qq];

        #pragma unroll
        for (int j = 0; j < 32; j++) {
            float4 w = w1p[j];
            float bj = b1p[j];
            unsigned long long w2r[8];
            #pragma unroll
            for (int qq = 0; qq < 8; qq++) w2r[qq] = w2p[j * 8 + qq];
            #pragma unroll
            for (int r = 0; r < R; r++) {
                float hj = bj;
                hj = fmaf(x0[r], w.x, hj); hj = fmaf(x1[r], w.y, hj);
                hj = fmaf(x2[r], w.z, hj); hj = fmaf(x3[r], w.w, hj);
                hj = fmaxf(hj, 0.f);
                unsigned hb = __float_as_uint(hj);
                unsigned long long hh;
                asm("mov.b64 %0, {%1, %2};" : "=l"(hh) : "r"(hb), "r"(hb));
                #pragma unroll
                for (int qq = 0; qq < 8; qq++) acc[r][qq] = ffma2(hh, w2r[qq], acc[r][qq]);
            }
        }

        // ---- per-row attention / LN / head ----
        #pragma unroll
        for (int r = 0; r < R; r++) {
            float e[16];
            #pragma unroll
            for (int qq = 0; qq < 8; qq++) {
                unsigned lo, hi;
                asm("mov.b64 {%0, %1}, %2;" : "=r"(lo), "=r"(hi) : "l"(acc[r][qq]));
                e[2 * qq]     = fmaxf(__uint_as_float(lo), 0.f);
                e[2 * qq + 1] = fmaxf(__uint_as_float(hi), 0.f);
            }

            // scores: dot(self_enc, e); self enc shuffled inline from lane 15
            float sc = 0.f;
            #pragma unroll
            for (int d = 0; d < 16; d++)
                sc = fmaf(__shfl_sync(FULLMASK, e[d], 15), e[d], sc);
            sc *= 0.25f;
            const bool active = (lane != 15);
            float p = active ? __expf(sc) : 0.f;   // bounded scores: no max-sub needed
            float ps = p;
            #pragma unroll
            for (int o = 1; o < 16; o <<= 1) ps += __shfl_xor_sync(FULLMASK, ps, o);
            const float aw = p / ps;

            // reduce-scatter of aw*e over the 16-lane half: lane ends with pooled[q16]
            float A8[8];
            {
                const bool hb = (q16 & 8) != 0;
                #pragma unroll
                for (int i = 0; i < 8; i++) {
                    float kp = hb ? e[i + 8] : e[i];
                    float sd = hb ? e[i]     : e[i + 8];
                    A8[i] = fmaf(aw, kp, __shfl_xor_sync(FULLMASK, aw * sd, 8));
                }
            }
            float A4[4];
            {
                const bool hb = (q16 & 4) != 0;
                #pragma unroll
                for (int i = 0; i < 4; i++) {
                    float kp = hb ? A8[i + 4] : A8[i];
                    float sd = hb ? A8[i]     : A8[i + 4];
                    A4[i] = kp + __shfl_xor_sync(FULLMASK, sd, 4);
                }
            }
            float A2[2];
            {
                const bool hb = (q16 & 2) != 0;
                #pragma unroll
                for (int i = 0; i < 2; i++) {
                    float kp = hb ? A4[i + 2] : A4[i];
                    float sd = hb ? A4[i]     : A4[i + 2];
                    A2[i] = kp + __shfl_xor_sync(FULLMASK, sd, 2);
                }
            }
            float pooled;
            {
                const bool hb = (q16 & 1) != 0;
                float kp = hb ? A2[1] : A2[0];
                float sd = hb ? A2[0] : A2[1];
                pooled = kp + __shfl_xor_sync(FULLMASK, sd, 1);
            }

            // LayerNorm over the 16 distributed values
            float s1 = pooled;
            #pragma unroll
            for (int o = 1; o < 16; o <<= 1) s1 += __shfl_xor_sync(FULLMASK, s1, o);
            const float mu = s1 * (1.f / 16.f);
            const float tdev = pooled - mu;
            float v2 = tdev * tdev;
            #pragma unroll
            for (int o = 1; o < 16; o <<= 1) v2 += __shfl_xor_sync(FULLMASK, v2, o);
            const float inv = rsqrtf(v2 * (1.f / 16.f) + 1e-5f);
            const float myn = fmaxf(fmaf(tdev * inv, lnG, lnB), 0.f);

            // swap across halves: lane gets both pools' value at d=q16
            const float oth = __shfl_xor_sync(FULLMASK, myn, 16);
            const float fp = lower ? oth : myn;   // food pool[q16]
            const float op = lower ? myn : oth;   // other pool[q16]

            // ---- head layer 1: merged(48) -> 32, weights via LDS.128 ----
            float hv = aB1;
            #pragma unroll
            for (int dq = 0; dq < 4; dq++) {
                float4 w = aw1t[dq];
                hv = fmaf(__shfl_sync(FULLMASK, e[4 * dq + 0], 15), w.x, hv);
                hv = fmaf(__shfl_sync(FULLMASK, e[4 * dq + 1], 15), w.y, hv);
                hv = fmaf(__shfl_sync(FULLMASK, e[4 * dq + 2], 15), w.z, hv);
                hv = fmaf(__shfl_sync(FULLMASK, e[4 * dq + 3], 15), w.w, hv);
            }
            #pragma unroll
            for (int dq = 0; dq < 4; dq++) {
                float4 w = aw1t[4 + dq];
                hv = fmaf(__shfl_sync(FULLMASK, fp, 4 * dq + 0, 16), w.x, hv);
                hv = fmaf(__shfl_sync(FULLMASK, fp, 4 * dq + 1, 16), w.y, hv);
                hv = fmaf(__shfl_sync(FULLMASK, fp, 4 * dq + 2, 16), w.z, hv);
                hv = fmaf(__shfl_sync(FULLMASK, fp, 4 * dq + 3, 16), w.w, hv);
            }
            #pragma unroll
            for (int dq = 0; dq < 4; dq++) {
                float4 w = aw1t[8 + dq];
                hv = fmaf(__shfl_sync(FULLMASK, op, 4 * dq + 0, 16), w.x, hv);
                hv = fmaf(__shfl_sync(FULLMASK, op, 4 * dq + 1, 16), w.y, hv);
                hv = fmaf(__shfl_sync(FULLMASK, op, 4 * dq + 2, 16), w.z, hv);
                hv = fmaf(__shfl_sync(FULLMASK, op, 4 * dq + 3, 16), w.w, hv);
            }
            hv = fmaxf(hv, 0.01f * hv);

            // ---- head layer 2: 32 -> 32 ----
            float h2 = aB2;
            #pragma unroll
            for (int jq = 0; jq < 8; jq++) {
                float4 w = aw2t[jq];
                h2 = fmaf(__shfl_sync(FULLMASK, hv, 4 * jq + 0), w.x, h2);
                h2 = fmaf(__shfl_sync(FULLMASK, hv, 4 * jq + 1), w.y, h2);
                h2 = fmaf(__shfl_sync(FULLMASK, hv, 4 * jq + 2), w.z, h2);
                h2 = fmaf(__shfl_sync(FULLMASK, hv, 4 * jq + 3), w.w, h2);
            }
            h2 = fmaxf(h2, 0.01f * h2);

            // ---- head layer 3: 32 -> 2 + tanh ----
            float p0 = h2 * w3a;
            float p1 = h2 * w3b;
            #pragma unroll
            for (int o = 16; o >= 1; o >>= 1) {
                p0 += __shfl_xor_sync(FULLMASK, p0, o);
                p1 += __shfl_xor_sync(FULLMASK, p1, o);
            }
            if (lane == 0) {
                float2 rr;
                rr.x = tanhf(p0 + b3a);
                rr.y = tanhf(p1 + b3b);
                *reinterpret_cast<float2*>(out + (size_t)(row0 + r) * 2) = rr;
            }
        }
    }
}

extern "C" void kernel_launch(void* const* d_in, const int* in_sizes, int n_in,
                              void* d_out, int out_size) {
    (void)in_sizes; (void)n_in; (void)out_size;
    dim3 grid(444), block(128);   // 148 SM x 3 CTAs, 12 warps/SM
    actor_fused_kernel<<<grid, block>>>(
        (const float*)d_in[0],
        (const float*)d_in[1],  (const float*)d_in[2],
        (const float*)d_in[3],  (const float*)d_in[4],
        (const float*)d_in[5],  (const float*)d_in[6],
        (const float*)d_in[7],  (const float*)d_in[8],
        (const float*)d_in[9],  (const float*)d_in[10],
        (const float*)d_in[11], (const float*)d_in[12],
        (const float*)d_in[13], (const float*)d_in[14],
        (const float*)d_in[15], (const float*)d_in[16],
        (const float*)d_in[17], (const float*)d_in[18],
        (const float*)d_in[19], (const float*)d_in[20],
        (const float*)d_in[21], (const float*)d_in[22],
        (float*)d_out);
}